// round 2
// baseline (speedup 1.0000x reference)
#include <cuda_runtime.h>
#include <cstdint>

// Problem constants (fixed shapes from reference)
#define N_TOK   49
#define C_DIM   256
#define H_NUM   8
#define HD      32
#define B_WIN   4096
#define NW_MASK 63          // nW = 64 -> mask idx = b & 63
#define M_ROWS  (B_WIN * N_TOK)   // 200704
#define QKV_N   (3 * C_DIM)       // 768

// Scratch (allocation-free rule: __device__ globals)
// layout: g_qkv[((b*8 + h)*3 + which)*49*32 + n*32 + d]
__device__ float g_qkv[(size_t)B_WIN * H_NUM * 3 * N_TOK * HD];   // 616 MB
// layout: g_attn[(b*49 + n)*256 + h*32 + d]
__device__ float g_attn[(size_t)M_ROWS * C_DIM];                  // 205 MB

// ---------------------------------------------------------------------------
// tf32 helpers
// ---------------------------------------------------------------------------
__device__ __forceinline__ float to_tf32(float x) {
    uint32_t u;
    asm("cvt.rna.tf32.f32 %0, %1;" : "=r"(u) : "f"(x));
    return __uint_as_float(u);
}

__device__ __forceinline__ void mma_tf32(float c[4], const uint32_t a[4], const uint32_t b[2]) {
    asm volatile(
        "mma.sync.aligned.m16n8k8.row.col.f32.tf32.tf32.f32 "
        "{%0,%1,%2,%3}, {%4,%5,%6,%7}, {%8,%9}, {%0,%1,%2,%3};"
        : "+f"(c[0]), "+f"(c[1]), "+f"(c[2]), "+f"(c[3])
        : "r"(a[0]), "r"(a[1]), "r"(a[2]), "r"(a[3]), "r"(b[0]), "r"(b[1]));
}

// ---------------------------------------------------------------------------
// Shared tiled tf32 GEMM core: C[128 x 64] += X[128 x 256] * W^T
// X row-major [M,256]; W row-major [N,256] (so W == B col-major for row.col mma)
// As[m][k] stride 36, Bs[n][k] stride 36: conflict-free fragment LDS
// ---------------------------------------------------------------------------
__device__ __forceinline__ void gemm_tile_tf32(
    const float* __restrict__ X, const float* __restrict__ W,
    int mBase, int nBase,
    float (*As)[36], float (*Bs)[36],
    float acc[2][4][4])
{
    const int tid  = threadIdx.x;
    const int warp = tid >> 5, lane = tid & 31;
    const int wm = (warp & 3) * 32;     // 4 warps along M
    const int wn = (warp >> 2) * 32;    // 2 warps along N
    const int g = lane >> 2, t = lane & 3;

    for (int kc = 0; kc < C_DIM; kc += 32) {
        // load A tile: 128 x 32
#pragma unroll
        for (int p = 0; p < 4; p++) {
            int r = (tid >> 3) + p * 32;
            int c = (tid & 7) * 4;
            float4 v = *(const float4*)(X + (size_t)(mBase + r) * C_DIM + kc + c);
            As[r][c + 0] = to_tf32(v.x); As[r][c + 1] = to_tf32(v.y);
            As[r][c + 2] = to_tf32(v.z); As[r][c + 3] = to_tf32(v.w);
        }
        // load B tile: 64 x 32 (rows of W)
#pragma unroll
        for (int p = 0; p < 2; p++) {
            int r = (tid >> 3) + p * 32;
            int c = (tid & 7) * 4;
            float4 v = *(const float4*)(W + (size_t)(nBase + r) * C_DIM + kc + c);
            Bs[r][c + 0] = to_tf32(v.x); Bs[r][c + 1] = to_tf32(v.y);
            Bs[r][c + 2] = to_tf32(v.z); Bs[r][c + 3] = to_tf32(v.w);
        }
        __syncthreads();

#pragma unroll
        for (int ko = 0; ko < 32; ko += 8) {
            uint32_t a[2][4], bb[4][2];
#pragma unroll
            for (int mi = 0; mi < 2; mi++) {
                int row = wm + mi * 16 + g;
                a[mi][0] = __float_as_uint(As[row][ko + t]);
                a[mi][1] = __float_as_uint(As[row + 8][ko + t]);
                a[mi][2] = __float_as_uint(As[row][ko + t + 4]);
                a[mi][3] = __float_as_uint(As[row + 8][ko + t + 4]);
            }
#pragma unroll
            for (int ni = 0; ni < 4; ni++) {
                int col = wn + ni * 8 + g;
                bb[ni][0] = __float_as_uint(Bs[col][ko + t]);
                bb[ni][1] = __float_as_uint(Bs[col][ko + t + 4]);
            }
#pragma unroll
            for (int mi = 0; mi < 2; mi++)
#pragma unroll
                for (int ni = 0; ni < 4; ni++)
                    mma_tf32(acc[mi][ni], a[mi], bb[ni]);
        }
        __syncthreads();
    }
}

// ---------------------------------------------------------------------------
// Kernel 1: QKV GEMM  (M=200704, K=256, N=768), epilogue scatters to g_qkv
// ---------------------------------------------------------------------------
__global__ __launch_bounds__(256) void qkv_gemm_kernel(
    const float* __restrict__ X, const float* __restrict__ W,
    const float* __restrict__ bias)
{
    __shared__ float As[128][36];
    __shared__ float Bs[64][36];
    const int mBase = blockIdx.x * 128;
    const int nBase = blockIdx.y * 64;

    float acc[2][4][4] = {};
    gemm_tile_tf32(X, W, mBase, nBase, As, Bs, acc);

    const int tid  = threadIdx.x;
    const int warp = tid >> 5, lane = tid & 31;
    const int wm = (warp & 3) * 32, wn = (warp >> 2) * 32;
    const int g = lane >> 2, t = lane & 3;
    const float qscale = 0.17677669529663687f;  // 32^-0.5

#pragma unroll
    for (int mi = 0; mi < 2; mi++) {
#pragma unroll
        for (int ni = 0; ni < 4; ni++) {
            int gn = nBase + wn + ni * 8 + t * 2;
            float bv0 = bias[gn], bv1 = bias[gn + 1];
            int which = gn >> 8;          // 0:q 1:k 2:v
            int h = (gn >> 5) & 7;
            int d = gn & 31;
            float sc = (which == 0) ? qscale : 1.0f;
#pragma unroll
            for (int half = 0; half < 2; half++) {
                int gm = mBase + wm + mi * 16 + g + half * 8;
                int b = gm / 49;
                int r = gm - b * 49;
                float v0 = (acc[mi][ni][half * 2 + 0] + bv0) * sc;
                float v1 = (acc[mi][ni][half * 2 + 1] + bv1) * sc;
                size_t off = ((((size_t)b * 8 + h) * 3 + which) * 49 + r) * 32 + d;
                *(float2*)(g_qkv + off) = make_float2(v0, v1);
            }
        }
    }
}

// ---------------------------------------------------------------------------
// Kernel 2: per-(window, head) attention. grid = 32768, block = 256 (8 warps)
// Warps 0..6 each own 7 rows of the 49-row attention matrix.
// ---------------------------------------------------------------------------
__global__ __launch_bounds__(256) void attn_kernel(
    const float* __restrict__ mask, const float* __restrict__ bt)
{
    const int bh = blockIdx.x;
    const int b = bh >> 3;
    const int h = bh & 7;

    __shared__ float sq[N_TOK * HD];       // [i][d]
    __shared__ float skT[HD * N_TOK];      // [d][j]  (transposed)
    __shared__ float sv[N_TOK * HD];       // [j][d]
    __shared__ float sS[N_TOK * N_TOK];    // [i][j]

    const int tid = threadIdx.x;
    const float* base = g_qkv + (size_t)bh * 3 * (N_TOK * HD);

    // load q, v linear; k transposed  (1568 floats = 392 float4 each)
    for (int idx = tid; idx < 392; idx += 256) {
        ((float4*)sq)[idx] = ((const float4*)base)[idx];
    }
    for (int idx = tid; idx < 392; idx += 256) {
        float4 v = ((const float4*)(base + N_TOK * HD))[idx];
        int j = idx >> 3;
        int d = (idx & 7) * 4;
        skT[(d + 0) * N_TOK + j] = v.x;
        skT[(d + 1) * N_TOK + j] = v.y;
        skT[(d + 2) * N_TOK + j] = v.z;
        skT[(d + 3) * N_TOK + j] = v.w;
    }
    for (int idx = tid; idx < 392; idx += 256) {
        ((float4*)sv)[idx] = ((const float4*)(base + 2 * N_TOK * HD))[idx];
    }
    __syncthreads();

    const int w = tid >> 5, lane = tid & 31;
    const int i0 = w * 7;

    // S = q @ k^T  (warps 0..6 handle 7 rows each; lanes cover j and j+32)
    if (i0 < N_TOK) {
        float accA[7] = {}, accB[7] = {};
#pragma unroll 8
        for (int d = 0; d < HD; d++) {
            float kA = skT[d * N_TOK + lane];
            float kB = (lane < 17) ? skT[d * N_TOK + 32 + lane] : 0.0f;
#pragma unroll
            for (int r = 0; r < 7; r++) {
                float qv = sq[(i0 + r) * HD + d];
                accA[r] += qv * kA;
                accB[r] += qv * kB;
            }
        }
        const float* mrow = mask + (size_t)(b & NW_MASK) * (N_TOK * N_TOK);
#pragma unroll
        for (int r = 0; r < 7; r++) {
            int i = i0 + r;
            int ri = i / 7, ci = i - ri * 7;
            {
                int j = lane;
                int rj = j / 7, cj = j - rj * 7;
                int bidx = (ri - rj + 6) * 13 + (ci - cj + 6);
                sS[i * N_TOK + j] = accA[r] + bt[bidx * 8 + h] + mrow[i * N_TOK + j];
            }
            int j2 = lane + 32;
            if (j2 < N_TOK) {
                int rj = j2 / 7, cj = j2 - rj * 7;
                int bidx = (ri - rj + 6) * 13 + (ci - cj + 6);
                sS[i * N_TOK + j2] = accB[r] + bt[bidx * 8 + h] + mrow[i * N_TOK + j2];
            }
        }
    }
    __syncthreads();

    // softmax over each row
    if (tid < N_TOK) {
        float* row = sS + tid * N_TOK;
        float m = -1e30f;
#pragma unroll 7
        for (int j = 0; j < N_TOK; j++) m = fmaxf(m, row[j]);
        float s = 0.0f;
#pragma unroll 7
        for (int j = 0; j < N_TOK; j++) { float e = __expf(row[j] - m); row[j] = e; s += e; }
        float inv = 1.0f / s;
#pragma unroll 7
        for (int j = 0; j < N_TOK; j++) row[j] *= inv;
    }
    __syncthreads();

    // out = P @ v ; lanes over d, rows i0..i0+6 per warp
    if (i0 < N_TOK) {
        float acc[7] = {};
#pragma unroll 7
        for (int j = 0; j < N_TOK; j++) {
            float vv = sv[j * HD + lane];
#pragma unroll
            for (int r = 0; r < 7; r++)
                acc[r] += sS[(i0 + r) * N_TOK + j] * vv;
        }
        float* outp = g_attn + ((size_t)b * N_TOK) * C_DIM + h * HD + lane;
#pragma unroll
        for (int r = 0; r < 7; r++)
            outp[(size_t)(i0 + r) * C_DIM] = acc[r];
    }
}

// ---------------------------------------------------------------------------
// Kernel 3: projection GEMM (M=200704, K=256, N=256) -> d_out
// ---------------------------------------------------------------------------
__global__ __launch_bounds__(256) void proj_gemm_kernel(
    const float* __restrict__ W, const float* __restrict__ bias,
    float* __restrict__ out)
{
    __shared__ float As[128][36];
    __shared__ float Bs[64][36];
    const int mBase = blockIdx.x * 128;
    const int nBase = blockIdx.y * 64;

    float acc[2][4][4] = {};
    gemm_tile_tf32(g_attn, W, mBase, nBase, As, Bs, acc);

    const int tid  = threadIdx.x;
    const int warp = tid >> 5, lane = tid & 31;
    const int wm = (warp & 3) * 32, wn = (warp >> 2) * 32;
    const int g = lane >> 2, t = lane & 3;

#pragma unroll
    for (int mi = 0; mi < 2; mi++) {
#pragma unroll
        for (int ni = 0; ni < 4; ni++) {
            int gn = nBase + wn + ni * 8 + t * 2;
            float bv0 = bias[gn], bv1 = bias[gn + 1];
#pragma unroll
            for (int half = 0; half < 2; half++) {
                int gm = mBase + wm + mi * 16 + g + half * 8;
                float v0 = acc[mi][ni][half * 2 + 0] + bv0;
                float v1 = acc[mi][ni][half * 2 + 1] + bv1;
                *(float2*)(out + (size_t)gm * C_DIM + gn) = make_float2(v0, v1);
            }
        }
    }
}

// ---------------------------------------------------------------------------
extern "C" void kernel_launch(void* const* d_in, const int* in_sizes, int n_in,
                              void* d_out, int out_size)
{
    const float* x      = (const float*)d_in[0];
    const float* mask   = (const float*)d_in[1];
    const float* qkv_w  = (const float*)d_in[2];
    const float* qkv_b  = (const float*)d_in[3];
    const float* proj_w = (const float*)d_in[4];
    const float* proj_b = (const float*)d_in[5];
    const float* bt     = (const float*)d_in[6];
    float* out = (float*)d_out;

    qkv_gemm_kernel<<<dim3(M_ROWS / 128, QKV_N / 64), 256>>>(x, qkv_w, qkv_b);
    attn_kernel<<<B_WIN * H_NUM, 256>>>(mask, bt);
    proj_gemm_kernel<<<dim3(M_ROWS / 128, C_DIM / 64), 256>>>(proj_w, proj_b, out);
}